// round 16
// baseline (speedup 1.0000x reference)
#include <cuda_runtime.h>

// Gaussian-splat over-compositing, N pixels x K gaussians, sm_103a.
// R16: R13 scalar loop (passed @2.9e-6) with:
//  - __launch_bounds__(128, 16): force <=32 regs -> 16 blocks/SM, 64 warps
//  - c2 packed 4-per-float4: per-step LDS 3 -> 2.25
//  - unroll 4 over k
// Per px-step:
//   q = A x2 + B2 xy + C y2 + Dx x + Ey y + F     (5 FMA)
//   e = ex2(q);  w = fma(-d, e, e)                // e*(1-d), d = pa+eps
//   u_c = fma(u_c, g, col_c*w)   (3 channels)
//   d += w;  r = rcp(d);  g = fma(r, -eps, 1)     // pa/(pa+eps)
// Final: pa = d-eps; pc = u*r_last. Exact reference semantics (~1ulp/step).

#define MAXK 128
#define EPSC 1e-8f

__device__ __forceinline__ float ex2f_(float x) {
    float y; asm("ex2.approx.f32 %0, %1;" : "=f"(y) : "f"(x)); return y;
}
__device__ __forceinline__ float rcpf_(float x) {
    float y; asm("rcp.approx.f32 %0, %1;" : "=f"(y) : "f"(x)); return y;
}

// smem: spAB[k] = {A,B2,C,Dx}; spEF[k] = {Ey,F,c0,c1}; sc2v[k/4] = 4x c2
__device__ __forceinline__ void prep_params(float4* spAB, float4* spEF,
                                            float* sc2,
                                            const float* mu, const float* alpha,
                                            const float* color, const float* scales,
                                            const float* thetas, int K) {
    const float L2E = 1.44269504088896340736f;
    for (int k = threadIdx.x; k < K; k += blockDim.x) {
        float th = thetas[k];
        float c = cosf(th), s = sinf(th);
        float sx = fmaxf(scales[2 * k + 0], 0.1f);
        float sy = fmaxf(scales[2 * k + 1], 0.1f);
        float ix = 1.0f / (sx * sx);
        float iy = 1.0f / (sy * sy);
        float S00 = c * c * ix + s * s * iy;
        float S01 = c * s * (ix - iy);
        float S11 = s * s * ix + c * c * iy;
        float h = -0.5f * L2E;
        float A  = h * S00;
        float B2 = (2.0f * h) * S01;
        float C  = h * S11;
        float a  = fminf(fmaxf(alpha[k], 0.0f), 1.0f);
        float la = log2f(fmaxf(a, 1e-38f));
        float c0 = fminf(fmaxf(color[3 * k + 0], 0.0f), 255.0f);
        float c1 = fminf(fmaxf(color[3 * k + 1], 0.0f), 255.0f);
        float c2 = fminf(fmaxf(color[3 * k + 2], 0.0f), 255.0f);
        float mx = mu[2 * k + 0] - 256.0f;   // centered coords
        float my = mu[2 * k + 1] - 256.0f;
        float Dx = -(2.0f * A * mx + B2 * my);
        float Ey = -(B2 * mx + 2.0f * C * my);
        float F  = (A * mx * mx + B2 * mx * my + C * my * my) + la;
        spAB[k] = make_float4(A, B2, C, Dx);
        spEF[k] = make_float4(Ey, F, c0, c1);
        sc2[k]  = c2;
    }
}

template<int KT>
__global__ __launch_bounds__(128, 16)
void gs_splat_kernel(const float* __restrict__ pos,
                     const float* __restrict__ mu,
                     const float* __restrict__ alpha,
                     const float* __restrict__ color,
                     const float* __restrict__ scales,
                     const float* __restrict__ thetas,
                     float4* __restrict__ out,
                     int n, int K)
{
    __shared__ __align__(16) float4 spAB[MAXK];
    __shared__ __align__(16) float4 spEF[MAXK];
    __shared__ __align__(16) float4 sc2v[MAXK / 4];
    prep_params(spAB, spEF, (float*)sc2v, mu, alpha, color, scales, thetas, K);
    __syncthreads();

    int i = blockIdx.x * blockDim.x + threadIdx.x;
    bool valid = (i < n);
    const float2* pos2 = (const float2*)pos;
    float2 P = valid ? pos2[i] : make_float2(0.0f, 0.0f);

    float X = P.x - 256.0f;
    float Y = P.y - 256.0f;
    float X2 = X * X;
    float XY = X * Y;
    float Y2 = Y * Y;

    float u0 = 0.0f, u1 = 0.0f, u2 = 0.0f;   // scaled color numerators
    float d  = EPSC;                          // pa + eps
    float gC = 0.0f;                          // carry factor pa/(pa+eps)
    float rC = 0.0f;                          // last rcp(d)

    if (KT == 128) {
#pragma unroll 4
        for (int kb = 0; kb < 128; kb += 4) {
            float4 c2v = sc2v[kb >> 2];
#pragma unroll
            for (int j = 0; j < 4; j++) {
                int k = kb + j;
                float c2 = (j == 0) ? c2v.x : (j == 1) ? c2v.y
                         : (j == 2) ? c2v.z : c2v.w;
                float4 p0 = spAB[k];   // A, B2, C, Dx
                float4 p1 = spEF[k];   // Ey, F, c0, c1

                float t = fmaf(p1.x, Y, p1.y);     // Ey*y + F
                t = fmaf(p0.w, X, t);              // + Dx*x
                t = fmaf(p0.z, Y2, t);             // + C*y2
                t = fmaf(p0.y, XY, t);             // + B2*xy
                float q = fmaf(p0.x, X2, t);       // + A*x2

                float e = ex2f_(q);                // alpha_k * gaussian
                float w = fmaf(-d, e, e);          // e*(1-d)
                u0 = fmaf(u0, gC, p1.z * w);
                u1 = fmaf(u1, gC, p1.w * w);
                u2 = fmaf(u2, gC, c2 * w);
                d += w;
                rC = rcpf_(d);
                gC = fmaf(rC, -EPSC, 1.0f);
            }
        }
    } else {
        const float* sc2 = (const float*)sc2v;
#pragma unroll 4
        for (int k = 0; k < K; k++) {
            float4 p0 = spAB[k];
            float4 p1 = spEF[k];
            float c2  = sc2[k];

            float t = fmaf(p1.x, Y, p1.y);
            t = fmaf(p0.w, X, t);
            t = fmaf(p0.z, Y2, t);
            t = fmaf(p0.y, XY, t);
            float q = fmaf(p0.x, X2, t);

            float e = ex2f_(q);
            float w = fmaf(-d, e, e);
            u0 = fmaf(u0, gC, p1.z * w);
            u1 = fmaf(u1, gC, p1.w * w);
            u2 = fmaf(u2, gC, c2 * w);
            d += w;
            rC = rcpf_(d);
            gC = fmaf(rC, -EPSC, 1.0f);
        }
    }

    if (valid) {
        float pa = d - EPSC;
        out[i] = make_float4(fminf(fmaxf(u0 * rC, 0.0f), 255.0f),
                             fminf(fmaxf(u1 * rC, 0.0f), 255.0f),
                             fminf(fmaxf(u2 * rC, 0.0f), 255.0f),
                             fminf(fmaxf(pa, 0.0f), 1.0f) * 255.0f);
    }
}

extern "C" void kernel_launch(void* const* d_in, const int* in_sizes, int n_in,
                              void* d_out, int out_size)
{
    const float* pos    = (const float*)d_in[0];
    const float* mu     = (const float*)d_in[1];
    const float* alpha  = (const float*)d_in[2];
    const float* color  = (const float*)d_in[3];
    const float* scales = (const float*)d_in[4];
    const float* thetas = (const float*)d_in[5];

    int n = in_sizes[0] / 2;     // pixels
    int K = in_sizes[2];         // gaussians
    if (K > MAXK) K = MAXK;

    const int threads = 128;
    int grid = (n + threads - 1) / threads;

    if (K == 128) {
        gs_splat_kernel<128><<<grid, threads>>>(pos, mu, alpha, color, scales,
                                                thetas, (float4*)d_out, n, K);
    } else {
        gs_splat_kernel<0><<<grid, threads>>>(pos, mu, alpha, color, scales,
                                              thetas, (float4*)d_out, n, K);
    }
}